// round 7
// baseline (speedup 1.0000x reference)
#include <cuda_runtime.h>
#include <cuda_bf16.h>
#include <cstdint>

// Problem constants (fixed by reference: BATCH=8, SEQ=D_MODEL=MAX_LEN=512)
#define BB   8
#define S    512
#define D    512

// scratch: extra[b*S + i] = sum_{j>i} q[b,i,j]
__device__ float g_extra[BB * S];

// ---------------------------------------------------------------------------
// Kernel 1: suffix sums. One warp per (b,i) row.
// ---------------------------------------------------------------------------
__global__ void suffix_sum_kernel(const float* __restrict__ q) {
    int row  = blockIdx.x * 8 + (threadIdx.x >> 5);   // 0..4095
    int lane = threadIdx.x & 31;
    int i    = row & (S - 1);
    const float* qrow = q + (size_t)row * D;
    float s = 0.f;
    for (int j = i + 1 + lane; j < S; j += 32) s += qrow[j];
    #pragma unroll
    for (int o = 16; o; o >>= 1) s += __shfl_xor_sync(0xFFFFFFFFu, s, o);
    if (lane == 0) g_extra[row] = s;
}

// ---------------------------------------------------------------------------
// Kernel 2: fused GEMM, contraction length 2*D = 1024.
//   c in [0,512):    A[i,c] = q[b,i,c]              B[c,k] = K[b,k,c]
//   c in [512,1024): p=c-512
//                    A[i,c] = (p<=i)?q[b,i,i-p]:0   B[c,k] = E[p,k]
// Epilogue: acc += g_extra[b,i] * E[0,k]
//   (bias[b,i,k] = sum_j q[b,i,j]*E[clip(i-j,0,511),k]
//    = sum_{p<=i} q[b,i,i-p]*E[p,k] + (sum_{j>i} q[b,i,j])*E[0,k])
//
// 128x128 output tile, BK=16, 256 threads, 8x8 micro-tile,
// register-staged global prefetch + double-buffered smem (1 BAR/iter).
// Grid = 4 x 4 x 8 = 128 CTAs: exactly one wave on 148 SMs.
// ---------------------------------------------------------------------------
#define BM 128
#define BN 128
#define BK 16
#define TM 8
#define TN 8
#define PAD 4
#define NTILES (2 * D / BK)   // 64

__global__ __launch_bounds__(256, 1)
void relpos_gemm_kernel(const float* __restrict__ q,
                        const float* __restrict__ kmat,
                        const float* __restrict__ E,
                        float* __restrict__ out) {
    __shared__ float As[2][BK][BM + PAD];   // As[buf][c][i]
    __shared__ float Bs[2][BK][BN + PAD];   // Bs[buf][c][k]

    const int tid = threadIdx.x;
    const int b   = blockIdx.z;
    const int i0  = blockIdx.y * BM;
    const int k0  = blockIdx.x * BN;

    const int tx = tid & 15;    // k-direction micro-tile index
    const int ty = tid >> 4;    // i-direction micro-tile index

    float acc[TM][TN];
    #pragma unroll
    for (int a = 0; a < TM; a++)
        #pragma unroll
        for (int c = 0; c < TN; c++) acc[a][c] = 0.f;

    // ---- load-thread mappings (each thread moves 8 A-floats + 8 B-floats) ----
    const int ld_row = tid >> 1;          // 0..127
    const int ld_cg  = (tid & 1) * 8;     // 0 or 8
    const int e_c    = tid >> 4;          // 0..15 (E-half B mapping)
    const int e_kg   = (tid & 15) * 8;    // 0..120

    const int   i_glob = i0 + ld_row;
    const float* qrowA = q    + ((size_t)b * S + i_glob) * D;
    const float* krowB = kmat + ((size_t)b * S + (k0 + ld_row)) * D;

    float ar[8], br[8];

    // epilogue operands, prefetched during the last tile's compute
    float e0[TN];
    float extv[TM];

    // ---------------- prologue: tile 0 (both halves < D) into buf 0 ----------
    {
        const float4 a0 = *(const float4*)(qrowA + ld_cg);
        const float4 a1 = *(const float4*)(qrowA + ld_cg + 4);
        const float4 b0 = *(const float4*)(krowB + ld_cg);
        const float4 b1 = *(const float4*)(krowB + ld_cg + 4);
        As[0][ld_cg + 0][ld_row] = a0.x; As[0][ld_cg + 1][ld_row] = a0.y;
        As[0][ld_cg + 2][ld_row] = a0.z; As[0][ld_cg + 3][ld_row] = a0.w;
        As[0][ld_cg + 4][ld_row] = a1.x; As[0][ld_cg + 5][ld_row] = a1.y;
        As[0][ld_cg + 6][ld_row] = a1.z; As[0][ld_cg + 7][ld_row] = a1.w;
        Bs[0][ld_cg + 0][ld_row] = b0.x; Bs[0][ld_cg + 1][ld_row] = b0.y;
        Bs[0][ld_cg + 2][ld_row] = b0.z; Bs[0][ld_cg + 3][ld_row] = b0.w;
        Bs[0][ld_cg + 4][ld_row] = b1.x; Bs[0][ld_cg + 5][ld_row] = b1.y;
        Bs[0][ld_cg + 6][ld_row] = b1.z; Bs[0][ld_cg + 7][ld_row] = b1.w;
    }
    __syncthreads();

    for (int t = 0; t < NTILES; t++) {
        const int buf = t & 1;
        const int cbn = (t + 1) * BK;
        const bool have_next = (t + 1 < NTILES);

        // ---- prefetch tile t+1 into registers (overlaps compute below) ----
        if (have_next) {
            // A half
            if (cbn < D) {
                const float4 a0 = *(const float4*)(qrowA + cbn + ld_cg);
                const float4 a1 = *(const float4*)(qrowA + cbn + ld_cg + 4);
                ar[0]=a0.x; ar[1]=a0.y; ar[2]=a0.z; ar[3]=a0.w;
                ar[4]=a1.x; ar[5]=a1.y; ar[6]=a1.z; ar[7]=a1.w;
            } else {
                const int pbase = cbn - D + ld_cg;
                #pragma unroll
                for (int u = 0; u < 8; u++) {
                    const int p = pbase + u;
                    ar[u] = (p <= i_glob) ? qrowA[i_glob - p] : 0.f;
                }
            }
            // B half
            if (cbn < D) {
                const float4 b0 = *(const float4*)(krowB + cbn + ld_cg);
                const float4 b1 = *(const float4*)(krowB + cbn + ld_cg + 4);
                br[0]=b0.x; br[1]=b0.y; br[2]=b0.z; br[3]=b0.w;
                br[4]=b1.x; br[5]=b1.y; br[6]=b1.z; br[7]=b1.w;
            } else {
                const int p = cbn - D + e_c;
                const float* erow = E + (size_t)p * D + k0 + e_kg;
                const float4 b0 = *(const float4*)(erow);
                const float4 b1 = *(const float4*)(erow + 4);
                br[0]=b0.x; br[1]=b0.y; br[2]=b0.z; br[3]=b0.w;
                br[4]=b1.x; br[5]=b1.y; br[6]=b1.z; br[7]=b1.w;
            }
        } else {
            // last iteration: issue epilogue loads so they drain behind FMAs
            const float4 ea = *(const float4*)(E + k0 + tx * TN);
            const float4 eb = *(const float4*)(E + k0 + tx * TN + 4);
            e0[0]=ea.x; e0[1]=ea.y; e0[2]=ea.z; e0[3]=ea.w;
            e0[4]=eb.x; e0[5]=eb.y; e0[6]=eb.z; e0[7]=eb.w;
            #pragma unroll
            for (int a = 0; a < TM; a++)
                extv[a] = g_extra[b * S + i0 + ty * TM + a];
        }

        // ---- compute tile t from smem[buf]: 16 c-steps x 64 FMA ----
        #pragma unroll
        for (int c = 0; c < BK; c++) {
            float af[TM], bf[TN];
            const float4 a0 = *(const float4*)&As[buf][c][ty * TM];
            const float4 a1 = *(const float4*)&As[buf][c][ty * TM + 4];
            af[0]=a0.x; af[1]=a0.y; af[2]=a0.z; af[3]=a0.w;
            af[4]=a1.x; af[5]=a1.y; af[6]=a1.z; af[7]=a1.w;
            const float4 b0 = *(const float4*)&Bs[buf][c][tx * TN];
            const float4 b1 = *(const float4*)&Bs[buf][c][tx * TN + 4];
            bf[0]=b0.x; bf[1]=b0.y; bf[2]=b0.z; bf[3]=b0.w;
            bf[4]=b1.x; bf[5]=b1.y; bf[6]=b1.z; bf[7]=b1.w;
            #pragma unroll
            for (int a = 0; a < TM; a++)
                #pragma unroll
                for (int cc = 0; cc < TN; cc++)
                    acc[a][cc] = fmaf(af[a], bf[cc], acc[a][cc]);
        }

        // ---- commit staged regs into the OTHER buffer, single barrier ----
        if (have_next) {
            const int nb = buf ^ 1;
            #pragma unroll
            for (int u = 0; u < 8; u++) As[nb][ld_cg + u][ld_row] = ar[u];
            if (cbn < D) {
                #pragma unroll
                for (int u = 0; u < 8; u++) Bs[nb][ld_cg + u][ld_row] = br[u];
            } else {
                *(float4*)&Bs[nb][e_c][e_kg]     = make_float4(br[0], br[1], br[2], br[3]);
                *(float4*)&Bs[nb][e_c][e_kg + 4] = make_float4(br[4], br[5], br[6], br[7]);
            }
            __syncthreads();
        }
    }

    // ---- epilogue: + extra[b,i] * E[0,k], float4 stores ----
    #pragma unroll
    for (int a = 0; a < TM; a++) {
        const int i = i0 + ty * TM + a;
        const float ext = extv[a];
        float* orow = out + ((size_t)b * S + i) * S + k0 + tx * TN;
        float4 v0, v1;
        v0.x = fmaf(ext, e0[0], acc[a][0]);
        v0.y = fmaf(ext, e0[1], acc[a][1]);
        v0.z = fmaf(ext, e0[2], acc[a][2]);
        v0.w = fmaf(ext, e0[3], acc[a][3]);
        v1.x = fmaf(ext, e0[4], acc[a][4]);
        v1.y = fmaf(ext, e0[5], acc[a][5]);
        v1.z = fmaf(ext, e0[6], acc[a][6]);
        v1.w = fmaf(ext, e0[7], acc[a][7]);
        *(float4*)(orow)     = v0;
        *(float4*)(orow + 4) = v1;
    }
}

// ---------------------------------------------------------------------------
extern "C" void kernel_launch(void* const* d_in, const int* in_sizes, int n_in,
                              void* d_out, int out_size) {
    const float* q = (const float*)d_in[0];              // [8,512,512]
    const float* k = (const float*)d_in[1];              // [8,512,512]
    const float* e = (const float*)d_in[2];              // [512,512]
    float* out     = (float*)d_out;                      // [8,512,512]

    suffix_sum_kernel<<<(BB * S) / 8, 256>>>(q);

    dim3 grid(S / BN, S / BM, BB);   // (4, 4, 8) = 128 CTAs, one wave
    relpos_gemm_kernel<<<grid, 256>>>(q, k, e, out);
}

// round 17
// speedup vs baseline: 1.5966x; 1.5966x over previous
#include <cuda_runtime.h>
#include <cuda_bf16.h>
#include <mma.h>
#include <cstdint>

using namespace nvcuda;

// Problem constants (fixed by reference: BATCH=8, SEQ=D_MODEL=MAX_LEN=512)
#define BB 8
#define S  512
#define D  512

// ---------------- device scratch (static allocation: allowed) --------------
__device__ float g_extra[BB * S];                       // suffix sums
__device__ __nv_bfloat16 g_qh [BB*S*D], g_ql [BB*S*D];  // q hi/lo
__device__ __nv_bfloat16 g_qrh[BB*S*D], g_qrl[BB*S*D];  // reversed/shifted q hi/lo
__device__ __nv_bfloat16 g_kh [BB*S*D], g_kl [BB*S*D];  // k hi/lo
__device__ __nv_bfloat16 g_eth[S*D],    g_etl[S*D];     // E^T hi/lo

// ---------------------------------------------------------------------------
// Kernel 1: suffix sums extra[b,i] = sum_{j>i} q[b,i,j]. One warp per row.
// ---------------------------------------------------------------------------
__global__ void suffix_sum_kernel(const float* __restrict__ q) {
    int row  = blockIdx.x * 8 + (threadIdx.x >> 5);
    int lane = threadIdx.x & 31;
    int i    = row & (S - 1);
    const float* qrow = q + (size_t)row * D;
    float s = 0.f;
    for (int j = i + 1 + lane; j < S; j += 32) s += qrow[j];
    #pragma unroll
    for (int o = 16; o; o >>= 1) s += __shfl_xor_sync(0xFFFFFFFFu, s, o);
    if (lane == 0) g_extra[row] = s;
}

// ---------------------------------------------------------------------------
// Kernel 2: bf16 hi/lo split of q (+ reversed/shifted copy) and k.
// grid (BB*S, 2): y=0 -> q row (+qrev), y=1 -> k row.
// ---------------------------------------------------------------------------
__global__ void split_kernel(const float* __restrict__ q,
                             const float* __restrict__ k) {
    const int row = blockIdx.x;
    const int tid = threadIdx.x;
    if (blockIdx.y == 0) {
        const float* qrow = q + (size_t)row * D;
        const int i = row & (S - 1);
        for (int j = tid; j < D; j += 256) {
            float v = qrow[j];
            __nv_bfloat16 h = __float2bfloat16(v);
            g_qh[(size_t)row * D + j] = h;
            g_ql[(size_t)row * D + j] = __float2bfloat16(v - __bfloat162float(h));
        }
        for (int p = tid; p < D; p += 256) {
            float v = (p <= i) ? qrow[i - p] : 0.f;
            __nv_bfloat16 h = __float2bfloat16(v);
            g_qrh[(size_t)row * D + p] = h;
            g_qrl[(size_t)row * D + p] = __float2bfloat16(v - __bfloat162float(h));
        }
    } else {
        const float* krow = k + (size_t)row * D;
        for (int j = tid; j < D; j += 256) {
            float v = krow[j];
            __nv_bfloat16 h = __float2bfloat16(v);
            g_kh[(size_t)row * D + j] = h;
            g_kl[(size_t)row * D + j] = __float2bfloat16(v - __bfloat162float(h));
        }
    }
}

// ---------------------------------------------------------------------------
// Kernel 3: E^T hi/lo (Et[n,p] = E[p,n]) via tiled transpose.
// ---------------------------------------------------------------------------
__global__ void et_kernel(const float* __restrict__ E) {
    __shared__ float tile[32][33];
    const int p0 = blockIdx.y * 32, n0 = blockIdx.x * 32;
    for (int r = threadIdx.y; r < 32; r += 8)
        tile[r][threadIdx.x] = E[(size_t)(p0 + r) * D + n0 + threadIdx.x];
    __syncthreads();
    for (int r = threadIdx.y; r < 32; r += 8) {
        float v = tile[threadIdx.x][r];          // = E[p0+tx, n0+r]
        __nv_bfloat16 h = __float2bfloat16(v);
        size_t o = (size_t)(n0 + r) * D + p0 + threadIdx.x;
        g_eth[o] = h;
        g_etl[o] = __float2bfloat16(v - __bfloat162float(h));
    }
}

// ---------------------------------------------------------------------------
// Kernel 4: WMMA bf16 3-term GEMM (HMMA — target-portable, no tcgen05).
//   Per batch: C = A*B^T, A=[q|qrev] (512x1024), B=[k|Et] (512x1024),
//   expanded as Ah*Bh + Al*Bh + Ah*Bl with fp32 accumulators.
//   Epilogue: C += extra[b,i] * E[0,k].
// CTA tile 128x128, K-chunks CK=64, 16 chunks, 8 warps x (32x64) sub-tiles.
// Strides chosen for 32-byte fragment-pointer alignment (WMMA requirement):
//   TSTR=80 bf16 (160B rows), CSTR=136 fp32 (544B rows).
// ---------------------------------------------------------------------------
#define TLM 128
#define TLN 128
#define CK  64
#define NCHUNK 16
#define TSTR 80                       // smem tile stride (bf16 elems, 160B rows)
#define TILE_E (128 * TSTR)           // elems per tile (10240)
#define CSTR 136                      // staging stride (floats, 544B rows)
#define SMEM_TOTAL (4 * TILE_E * 2)   // 81920 B tiles >= 69632 B staging

__global__ __launch_bounds__(256, 1)
void relpos_wmma_kernel(const float* __restrict__ E, float* __restrict__ out) {
    extern __shared__ __align__(32) char smem[];
    __nv_bfloat16* tileA_h = (__nv_bfloat16*)smem;
    __nv_bfloat16* tileA_l = tileA_h + TILE_E;
    __nv_bfloat16* tileB_h = tileA_l + TILE_E;
    __nv_bfloat16* tileB_l = tileB_h + TILE_E;

    const int tid  = threadIdx.x;
    const int wid  = tid >> 5;
    const int lane = tid & 31;
    const int b  = blockIdx.z;
    const int i0 = blockIdx.y * TLM;
    const int k0 = blockIdx.x * TLN;
    const int wy = wid >> 1;          // 0..3 : 32-row band
    const int wx = wid & 1;           // 0..1 : 64-col band

    wmma::fragment<wmma::accumulator, 16, 16, 16, float> acc[2][4];
    #pragma unroll
    for (int m = 0; m < 2; m++)
        #pragma unroll
        for (int j = 0; j < 4; j++) wmma::fill_fragment(acc[m][j], 0.f);

    for (int gc = 0; gc < NCHUNK; gc++) {
        const int kc = (gc & 7) * CK;
        const __nv_bfloat16 *sAh, *sAl, *sBh, *sBl;
        const size_t qoff = ((size_t)b * S + i0) * D + kc;
        if (gc < 8) {
            const size_t ko = ((size_t)b * S + k0) * D + kc;
            sAh = g_qh + qoff;  sAl = g_ql + qoff;
            sBh = g_kh + ko;    sBl = g_kl + ko;
        } else {
            const size_t eo = (size_t)k0 * D + kc;
            sAh = g_qrh + qoff; sAl = g_qrl + qoff;
            sBh = g_eth + eo;   sBl = g_etl + eo;
        }
        // load 4 tiles: 128 rows x 64 bf16 each, uint4 per thread x4 iters
        const __nv_bfloat16* srcs[4] = {sAh, sAl, sBh, sBl};
        __nv_bfloat16* dsts[4] = {tileA_h, tileA_l, tileB_h, tileB_l};
        #pragma unroll
        for (int t4 = 0; t4 < 4; t4++) {
            const __nv_bfloat16* sp = srcs[t4];
            __nv_bfloat16* dp = dsts[t4];
            #pragma unroll
            for (int it = 0; it < 4; it++) {
                const int row  = it * 32 + (tid >> 3);
                const int col8 = (tid & 7) * 8;
                uint4 v = *(const uint4*)(sp + (size_t)row * D + col8);
                *(uint4*)(dp + row * TSTR + col8) = v;
            }
        }
        __syncthreads();

        // 3 passes: Ah*Bh, Al*Bh, Ah*Bl
        #pragma unroll
        for (int pass = 0; pass < 3; pass++) {
            const __nv_bfloat16* At = (pass == 1) ? tileA_l : tileA_h;
            const __nv_bfloat16* Bt = (pass == 2) ? tileB_l : tileB_h;
            #pragma unroll
            for (int kk = 0; kk < CK / 16; kk++) {
                wmma::fragment<wmma::matrix_a, 16, 16, 16, __nv_bfloat16,
                               wmma::row_major> af[2];
                wmma::fragment<wmma::matrix_b, 16, 16, 16, __nv_bfloat16,
                               wmma::col_major> bfr[4];
                #pragma unroll
                for (int m = 0; m < 2; m++)
                    wmma::load_matrix_sync(af[m],
                        At + (wy * 32 + m * 16) * TSTR + kk * 16, TSTR);
                #pragma unroll
                for (int j = 0; j < 4; j++)
                    wmma::load_matrix_sync(bfr[j],
                        Bt + (wx * 64 + j * 16) * TSTR + kk * 16, TSTR);
                #pragma unroll
                for (int m = 0; m < 2; m++)
                    #pragma unroll
                    for (int j = 0; j < 4; j++)
                        wmma::mma_sync(acc[m][j], af[m], bfr[j], acc[m][j]);
            }
        }
        __syncthreads();
    }

    // ---- epilogue: fragments -> smem staging -> +bias -> global ----
    float* stage = (float*)smem;
    #pragma unroll
    for (int m = 0; m < 2; m++)
        #pragma unroll
        for (int j = 0; j < 4; j++)
            wmma::store_matrix_sync(
                stage + (wy * 32 + m * 16) * CSTR + wx * 64 + j * 16,
                acc[m][j], CSTR, wmma::mem_row_major);
    __syncthreads();

    const float4 e0 = *(const float4*)(E + k0 + lane * 4);   // E row 0
    #pragma unroll
    for (int r = 0; r < 16; r++) {
        const int row = r * 8 + wid;
        const int i   = i0 + row;
        const float ext = g_extra[b * S + i];
        float4 v = *(float4*)(stage + row * CSTR + lane * 4);
        v.x += ext * e0.x; v.y += ext * e0.y;
        v.z += ext * e0.z; v.w += ext * e0.w;
        *(float4*)(out + ((size_t)b * S + i) * S + k0 + lane * 4) = v;
    }
}

// ---------------------------------------------------------------------------
extern "C" void kernel_launch(void* const* d_in, const int* in_sizes, int n_in,
                              void* d_out, int out_size) {
    const float* q = (const float*)d_in[0];   // [8,512,512]
    const float* k = (const float*)d_in[1];   // [8,512,512]
    const float* e = (const float*)d_in[2];   // [512,512]
    float* out     = (float*)d_out;           // [8,512,512]

    suffix_sum_kernel<<<(BB * S) / 8, 256>>>(q);
    split_kernel<<<dim3(BB * S, 2), 256>>>(q, k);
    et_kernel<<<dim3(16, 16), dim3(32, 8)>>>(e);

    cudaFuncSetAttribute(relpos_wmma_kernel,
                         cudaFuncAttributeMaxDynamicSharedMemorySize, SMEM_TOTAL);
    dim3 grid(S / TLN, S / TLM, BB);          // (4,4,8) = 128 CTAs, one wave
    relpos_wmma_kernel<<<grid, 256, SMEM_TOTAL>>>(e, out);
}